// round 5
// baseline (speedup 1.0000x reference)
#include <cuda_runtime.h>
#include <stdint.h>

#define S   128
#define B   256
#define H   16
#define NB  12
#define LUT_WORDS 128
#define THRESH 8

#define N_TOKENS  (S * B)              // 32768
#define N_MEMORY  (H * B * (1 << NB))  // 16777216
#define N_CONN    (H * B * NB)         // 49152

__device__ uint8_t g_headres[H * B * S];   // [h][n][i], 512 KB

// Decode a connection entry that may be int32 or float32 bits.
// Valid range is [0, 519). Float bits of any value >= 1.0 are > 518.
__device__ __forceinline__ int decode_conn(uint32_t raw) {
    return (raw <= 518u) ? (int)raw : (int)__uint_as_float(raw);
}

// One block per (h, n). 128 threads; thread t owns query row i = t.
__global__ __launch_bounds__(128) void soft_ram_main(
    const uint32_t* __restrict__ tokens,       // [S,B] int32 OR float32 bits, values {0,1}
    const float*    __restrict__ memory,       // [H,B,4096] f32
    const uint32_t* __restrict__ connections)  // [H,B,NB] int32 OR float32 bits
{
    __shared__ uint32_t s_lut[LUT_WORDS];
    __shared__ uint32_t s_Ak[S];
    __shared__ uint32_t s_Ap[S];

    const int blk = blockIdx.x;
    const int h = blk >> 8;
    const int n = blk & 255;
    const int t = threadIdx.x;
    const int warp = t >> 5, lane = t & 31;

    // 1. Binarize this neuron's 4096-float LUT into a 512B bitmap.
    const float* mem = memory + ((size_t)(h * B + n) << NB);
    for (int w = warp; w < LUT_WORDS; w += 4) {
        float v = mem[(w << 5) + lane];
        uint32_t bal = __ballot_sync(0xffffffffu, v > 0.0f);
        if (lane == 0) s_lut[w] = bal;
    }

    // 2. Decomposed address parts: addr(i,j) = Aq[i] | Ak[j] | Ap[i-j].
    //    Token bit test (raw != 0) works for int 1 and float 1.0f alike.
    const uint32_t* conn = connections + (size_t)(h * B + n) * NB;
    uint32_t aq = 0, ak = 0, ap = 0;
    #pragma unroll
    for (int b = 0; b < NB; b++) {
        int c = decode_conn(conn[b]);
        if (c < B) {
            aq |= (uint32_t)(tokens[t * B + c] != 0u) << b;
        } else if (c < 2 * B) {
            ak |= (uint32_t)(tokens[t * B + (c - B)] != 0u) << b;
        } else {
            ap |= ((uint32_t)(t >> (c - 2 * B)) & 1u) << b;
        }
    }
    s_Ak[t] = ak;
    s_Ap[t] = ap;
    __syncthreads();

    // 3. Causal XOR accumulation over keys j <= i.
    uint32_t p = 0;
    const int i = t;
    #pragma unroll 4
    for (int j = 0; j <= i; ++j) {
        uint32_t a = aq | s_Ak[j] | s_Ap[i - j];
        p ^= s_lut[a >> 5] >> (a & 31);
    }

    g_headres[(size_t)(h * B + n) * S + i] = (uint8_t)(p & 1u);
}

// Sum parities across heads, threshold, write FLOAT output.
__global__ __launch_bounds__(256) void soft_ram_reduce(float* __restrict__ out)
{
    const int tid = blockIdx.x * 256 + threadIdx.x;   // 0 .. B*S-1
    int s = 0;
    #pragma unroll
    for (int h = 0; h < H; h++)
        s += g_headres[(size_t)h * (B * S) + tid];
    const int n = tid >> 7;
    const int i = tid & (S - 1);
    out[i * B + n] = (s > THRESH) ? 1.0f : 0.0f;
}

extern "C" void kernel_launch(void* const* d_in, const int* in_sizes, int n_in,
                              void* d_out, int out_size)
{
    const uint32_t* tokens      = 0;
    const float*    memory      = 0;
    const uint32_t* connections = 0;

    // Pass 1: element counts.
    for (int k = 0; k < n_in; k++) {
        if      (in_sizes[k] == N_TOKENS && !tokens)      tokens      = (const uint32_t*)d_in[k];
        else if (in_sizes[k] == N_MEMORY && !memory)      memory      = (const float*)d_in[k];
        else if (in_sizes[k] == N_CONN   && !connections) connections = (const uint32_t*)d_in[k];
    }
    // Pass 2: byte counts.
    for (int k = 0; k < n_in; k++) {
        if      (in_sizes[k] == N_TOKENS * 4 && !tokens)      tokens      = (const uint32_t*)d_in[k];
        else if (in_sizes[k] == N_MEMORY * 4 && !memory)      memory      = (const float*)d_in[k];
        else if (in_sizes[k] == N_CONN * 4   && !connections) connections = (const uint32_t*)d_in[k];
    }
    // Pass 3: positional fallback (tokens, memory, connections).
    if (!tokens || !memory || !connections) {
        tokens      = (const uint32_t*)d_in[0];
        memory      = (const float*)d_in[1];
        connections = (const uint32_t*)d_in[2];
    }

    soft_ram_main<<<H * B, 128>>>(tokens, memory, connections);
    soft_ram_reduce<<<(B * S) / 256, 256>>>((float*)d_out);
}

// round 6
// speedup vs baseline: 1.4528x; 1.4528x over previous
#include <cuda_runtime.h>
#include <stdint.h>

#define S   128
#define B   256
#define H   16
#define NB  12
#define LUT_WORDS 128
#define THRESH 8

#define N_TOKENS  (S * B)              // 32768
#define N_MEMORY  (H * B * (1 << NB))  // 16777216
#define N_CONN    (H * B * NB)         // 49152

__device__ uint8_t  g_headres[H * B * S];   // [h][n][i]
__device__ unsigned g_count[B];             // last-block counters (self-resetting)
__device__ uint32_t g_tokpack[S * 8];       // bit-packed tokens [row][word]

// Connection entry may be int32 or float32 bits; range [0,519). Float bits of
// any value >= 1.0 exceed 518, so the test is unambiguous.
__device__ __forceinline__ int decode_conn(uint32_t raw) {
    return (raw <= 518u) ? (int)raw : (int)__uint_as_float(raw);
}

// Pack tokens[S][B] (0/1 words) into bitmaps: 128 warps, one row each.
__global__ __launch_bounds__(128) void pack_tokens(const uint32_t* __restrict__ tokens)
{
    const int gw   = blockIdx.x * 4 + (threadIdx.x >> 5);  // global warp = row
    const int lane = threadIdx.x & 31;
    #pragma unroll
    for (int w = 0; w < 8; w++) {
        uint32_t v   = tokens[gw * B + w * 32 + lane];
        uint32_t bal = __ballot_sync(0xffffffffu, v != 0u);
        if (lane == 0) g_tokpack[gw * 8 + w] = bal;
    }
}

// One block per (h, n). 128 threads; thread t owns query row i = t.
// Last block to finish for a given n also performs the head-majority reduce.
__global__ __launch_bounds__(128) void soft_ram_main(
    const float*    __restrict__ memory,       // [H,B,4096] f32
    const uint32_t* __restrict__ connections,  // [H,B,NB]
    float*          __restrict__ out)          // [S,B] f32
{
    __shared__ __align__(16) uint32_t s_lut[LUT_WORDS];
    __shared__ __align__(16) uint32_t s_Ak[S];
    __shared__ uint32_t s_Ap[S];
    __shared__ uint32_t s_tok[S * 9];          // padded rows: 9 words (conflict-free)
    __shared__ int s_last;

    const int blk = blockIdx.x;
    const int h = blk >> 8;
    const int n = blk & 255;
    const int t = threadIdx.x;
    const int warp = t >> 5, lane = t & 31;

    // Stage this thread's packed token row (coalesced 32B per thread).
    {
        const uint4* src = (const uint4*)g_tokpack;
        uint4 a = src[t * 2], b = src[t * 2 + 1];
        s_tok[t * 9 + 0] = a.x; s_tok[t * 9 + 1] = a.y;
        s_tok[t * 9 + 2] = a.z; s_tok[t * 9 + 3] = a.w;
        s_tok[t * 9 + 4] = b.x; s_tok[t * 9 + 5] = b.y;
        s_tok[t * 9 + 6] = b.z; s_tok[t * 9 + 7] = b.w;
    }

    // Binarize this neuron's 4096-float LUT into a 512B bitmap.
    const float* mem = memory + ((size_t)(h * B + n) << NB);
    for (int w = warp; w < LUT_WORDS; w += 4) {
        uint32_t bal = __ballot_sync(0xffffffffu, mem[(w << 5) + lane] > 0.0f);
        if (lane == 0) s_lut[w] = bal;
    }
    __syncthreads();

    // Decomposed address parts: addr(i,j) = Aq[i] | Ak[j] | Ap[i-j].
    const uint32_t* conn = connections + (size_t)(h * B + n) * NB;
    uint32_t aq = 0, ak = 0, ap = 0;
    #pragma unroll
    for (int b = 0; b < NB; b++) {
        int c = decode_conn(conn[b]);
        if (c < B) {
            aq |= ((s_tok[t * 9 + (c >> 5)] >> (c & 31)) & 1u) << b;
        } else if (c < 2 * B) {
            int cc = c - B;
            ak |= ((s_tok[t * 9 + (cc >> 5)] >> (cc & 31)) & 1u) << b;
        } else {
            ap |= ((uint32_t)(t >> (c - 2 * B)) & 1u) << b;
        }
    }
    s_Ak[t] = ak;
    s_Ap[t] = ap;
    __syncthreads();

    // Causal XOR accumulation over keys j <= i. Bit of interest lands in bit 0
    // via rotate (funnelshift handles shift mod 32); upper bits are garbage.
    uint32_t p = 0;
    const int i = t;
    int j = 0;
    const int full = (i + 1) & ~3;
    #pragma unroll 2
    for (; j < full; j += 4) {
        uint4 k4 = *reinterpret_cast<const uint4*>(&s_Ak[j]);  // 16B-aligned broadcast
        uint32_t a0 = aq | k4.x | s_Ap[i - j];
        uint32_t a1 = aq | k4.y | s_Ap[i - j - 1];
        uint32_t a2 = aq | k4.z | s_Ap[i - j - 2];
        uint32_t a3 = aq | k4.w | s_Ap[i - j - 3];
        uint32_t w0 = s_lut[a0 >> 5], w1 = s_lut[a1 >> 5];
        uint32_t w2 = s_lut[a2 >> 5], w3 = s_lut[a3 >> 5];
        p ^= __funnelshift_r(w0, w0, a0) ^ __funnelshift_r(w1, w1, a1)
           ^ __funnelshift_r(w2, w2, a2) ^ __funnelshift_r(w3, w3, a3);
    }
    for (; j <= i; ++j) {
        uint32_t a = aq | s_Ak[j] | s_Ap[i - j];
        uint32_t w = s_lut[a >> 5];
        p ^= __funnelshift_r(w, w, a);
    }

    g_headres[(size_t)(h * B + n) * S + t] = (uint8_t)(p & 1u);

    // Last-block-per-n reduce (threadFenceReduction pattern).
    __threadfence();
    if (t == 0) {
        unsigned old = atomicAdd(&g_count[n], 1u);
        s_last = (old == H - 1) ? 1 : 0;
    }
    __syncthreads();
    if (s_last) {
        __threadfence();   // ensure we see all heads' results past L1
        int ssum = 0;
        #pragma unroll
        for (int hh = 0; hh < H; hh++)
            ssum += g_headres[(size_t)(hh * B + n) * S + t];
        out[t * B + n] = (ssum > THRESH) ? 1.0f : 0.0f;
        if (t == 0) g_count[n] = 0;   // reset for next graph replay
    }
}

extern "C" void kernel_launch(void* const* d_in, const int* in_sizes, int n_in,
                              void* d_out, int out_size)
{
    const uint32_t* tokens      = 0;
    const float*    memory      = 0;
    const uint32_t* connections = 0;

    for (int k = 0; k < n_in; k++) {
        if      (in_sizes[k] == N_TOKENS && !tokens)      tokens      = (const uint32_t*)d_in[k];
        else if (in_sizes[k] == N_MEMORY && !memory)      memory      = (const float*)d_in[k];
        else if (in_sizes[k] == N_CONN   && !connections) connections = (const uint32_t*)d_in[k];
    }
    for (int k = 0; k < n_in; k++) {
        if      (in_sizes[k] == N_TOKENS * 4 && !tokens)      tokens      = (const uint32_t*)d_in[k];
        else if (in_sizes[k] == N_MEMORY * 4 && !memory)      memory      = (const float*)d_in[k];
        else if (in_sizes[k] == N_CONN * 4   && !connections) connections = (const uint32_t*)d_in[k];
    }
    if (!tokens || !memory || !connections) {
        tokens      = (const uint32_t*)d_in[0];
        memory      = (const float*)d_in[1];
        connections = (const uint32_t*)d_in[2];
    }

    pack_tokens<<<32, 128>>>(tokens);
    soft_ram_main<<<H * B, 128>>>(memory, connections, (float*)d_out);
}